// round 10
// baseline (speedup 1.0000x reference)
#include <cuda_runtime.h>

// db4 single-level 2D DWT, circular padding (end), stride-2 cross-correlation.
// x: (96, 512, 512) f32 -> out: (96*4, 256, 256) f32, subband order ll,lh,hl,hh.
//
// Column pass FIRST (full-width stripes, coalesced streaming loads), then row
// pass from smem planes. lo/hi filter pairs evaluated with packed f32x2 FMA
// (Blackwell FFMA2): accumulator=(lo,hi), coef pair C[t]=(FL[t],FH[t]).

#define HH   512
#define WW   512
#define OWW  256
#define TH   8             // output rows per block (stripe height)
#define IN_R (2*TH + 6)    // 22 input rows per stripe
#define PW   520           // plane width: 512 + 8 wrap-halo cols

typedef unsigned long long u64;

static __device__ __forceinline__ u64 pk(float a, float b) {
    u64 r; asm("mov.b64 %0, {%1, %2};" : "=l"(r) : "f"(a), "f"(b)); return r;
}
static __device__ __forceinline__ void upk(u64 p, float& a, float& b) {
    asm("mov.b64 {%0, %1}, %2;" : "=f"(a), "=f"(b) : "l"(p));
}
static __device__ __forceinline__ void fma2(u64& d, u64 a, u64 b) {
    asm("fma.rn.f32x2 %0, %1, %2, %0;" : "+l"(d) : "l"(a), "l"(b));
}
static __device__ __forceinline__ void mul2(u64& d, u64 a, u64 b) {
    asm("mul.rn.f32x2 %0, %1, %2;" : "=l"(d) : "l"(a), "l"(b));
}

__global__ __launch_bounds__(512, 3) void dwt2d_db4_kernel(
    const float* __restrict__ x,
    float* __restrict__ out)
{
    __shared__ __align__(16) float s_lo[TH][PW];   // col-pass LO plane
    __shared__ __align__(16) float s_hi[TH][PW];   // col-pass HI plane

    const float FL[8] = {-0.010597401784997278f,  0.032883011666982945f,
                          0.030841381835986965f, -0.18703481171888114f,
                         -0.02798376941698385f,   0.6308807679295904f,
                          0.7148465705525415f,    0.23037781330885523f};
    const float FH[8] = {-0.23037781330885523f,   0.7148465705525415f,
                         -0.6308807679295904f,   -0.02798376941698385f,
                          0.18703481171888114f,   0.030841381835986965f,
                         -0.032883011666982945f, -0.010597401784997278f};

    // packed coefficient pairs (lo, hi) per tap — live in registers
    u64 C[8];
    #pragma unroll
    for (int t = 0; t < 8; t++) C[t] = pk(FL[t], FH[t]);

    const int tid = threadIdx.x;          // 0..511
    const int sy  = blockIdx.x;           // 0..31 stripe
    const int img = blockIdx.y;           // 0..95
    const int h0  = sy * TH;              // output row base
    const int r0  = 2 * h0;               // input row base

    const float* __restrict__ xin = x + (size_t)img * HH * WW;

    // ---- phase A: column pass, thread owns input column c = tid ----
    // Streams 22 rows (1 coalesced LDG.32 per row), ring of 4 packed (lo,hi)
    // accumulators; output j retires at tap t==7.
    {
        const int c = tid;
        u64 acc[4];
        #pragma unroll
        for (int k = 0; k < IN_R; k++) {
            float v = xin[(size_t)((r0 + k) & (HH - 1)) * WW + c];
            u64 vv = pk(v, v);
            #pragma unroll
            for (int j = 0; j < TH; j++) {
                const int t = k - 2 * j;
                if (t == 0) {
                    mul2(acc[j & 3], C[0], vv);
                } else if (t > 0 && t < 8) {
                    fma2(acc[j & 3], C[t], vv);
                }
                if (t == 7) {
                    float lo, hi; upk(acc[j & 3], lo, hi);
                    s_lo[j][c] = lo;
                    s_hi[j][c] = hi;
                    if (c < 8) {                    // wrap halo for row pass
                        s_lo[j][WW + c] = lo;
                        s_hi[j][WW + c] = hi;
                    }
                }
            }
        }
    }
    __syncthreads();

    // ---- phase B: row pass from smem planes ----
    // item = (plane, j, wp): output cols 2wp, 2wp+1 of output row h0+j.
    // acc0=(lo0,hi0) for col 2wp, acc1=(lo1,hi1) for col 2wp+1; packed values
    // are consumed immediately after packing (liveness 1).
    float* __restrict__ outi = out + (size_t)img * 4 * OWW * OWW;
    const size_t SB = (size_t)OWW * OWW;

    #pragma unroll
    for (int it = 0; it < 4; it++) {
        int idx = tid + it * 512;            // 0..2047
        int wp  = idx & 127;                 // col-pair index
        int j   = (idx >> 7) & (TH - 1);     // 0..7
        int pl  = idx >> 10;                 // 0..1
        const float* __restrict__ A = pl ? &s_hi[j][0] : &s_lo[j][0];

        // window A[4wp .. 4wp+9]; 16B-stride contiguous -> conflict-free
        float4 q0 = *(const float4*)(A + 4 * wp);
        float4 q1 = *(const float4*)(A + 4 * wp + 4);
        float2 q2 = *(const float2*)(A + 4 * wp + 8);
        float v[10] = {q0.x, q0.y, q0.z, q0.w,
                       q1.x, q1.y, q1.z, q1.w,
                       q2.x, q2.y};

        u64 a0, a1;
        #pragma unroll
        for (int p = 0; p < 10; p++) {
            u64 vp = pk(v[p], v[p]);
            if (p < 8) {
                if (p == 0) mul2(a0, C[0], vp);
                else        fma2(a0, C[p], vp);
            }
            if (p >= 2) {
                if (p == 2) mul2(a1, C[0], vp);
                else        fma2(a1, C[p - 2], vp);
            }
        }
        float lo0, hi0, lo1, hi1;
        upk(a0, lo0, hi0);
        upk(a1, lo1, hi1);

        int sbL = pl ? 1 : 0;    // row-lo result subband
        int sbH = pl ? 3 : 2;    // row-hi result subband
        size_t o = (size_t)(h0 + j) * OWW + 2 * wp;
        *(float2*)(outi + sbL * SB + o) = make_float2(lo0, lo1);
        *(float2*)(outi + sbH * SB + o) = make_float2(hi0, hi1);
    }
}

extern "C" void kernel_launch(void* const* d_in, const int* in_sizes, int n_in,
                              void* d_out, int out_size)
{
    const float* x = (const float*)d_in[0];   // (32,3,512,512) f32
    float* out = (float*)d_out;               // (32,12,256,256) f32

    dim3 grid(OWW / TH, 96);                  // (32 stripes, 96 images)
    dwt2d_db4_kernel<<<grid, 512>>>(x, out);
}

// round 11
// speedup vs baseline: 1.1688x; 1.1688x over previous
#include <cuda_runtime.h>

// db4 single-level 2D DWT, circular padding (end), stride-2 cross-correlation.
// x: (96, 512, 512) f32 -> out: (96*4, 256, 256) f32, subband order ll,lh,hl,hh.
//
// Column pass FIRST (full-width stripes). Phase A uses packed f32x2 FMA over
// ADJACENT COLUMN PAIRS: the loaded u64 (two neighboring pixels) is directly
// the FFMA2 operand -- zero pack instructions. Phase B is the proven scalar
// row pass from smem planes.

#define HH   512
#define WW   512
#define OWW  256
#define TH   8             // output rows per block (stripe height)
#define IN_R (2*TH + 6)    // 22 input rows per stripe
#define PW   520           // plane width: 512 + 8 wrap-halo cols
#define NT   256           // threads per block (thread owns 2 columns)

typedef unsigned long long u64;

static __device__ __forceinline__ u64 pk(float a, float b) {
    u64 r; asm("mov.b64 %0, {%1, %2};" : "=l"(r) : "f"(a), "f"(b)); return r;
}
static __device__ __forceinline__ void fma2(u64& d, u64 a, u64 b) {
    asm("fma.rn.f32x2 %0, %1, %2, %0;" : "+l"(d) : "l"(a), "l"(b));
}
static __device__ __forceinline__ void mul2(u64& d, u64 a, u64 b) {
    asm("mul.rn.f32x2 %0, %1, %2;" : "=l"(d) : "l"(a), "l"(b));
}

__global__ __launch_bounds__(NT, 4) void dwt2d_db4_kernel(
    const float* __restrict__ x,
    float* __restrict__ out)
{
    __shared__ __align__(16) float s_lo[TH][PW];   // col-pass LO plane
    __shared__ __align__(16) float s_hi[TH][PW];   // col-pass HI plane

    const float FL[8] = {-0.010597401784997278f,  0.032883011666982945f,
                          0.030841381835986965f, -0.18703481171888114f,
                         -0.02798376941698385f,   0.6308807679295904f,
                          0.7148465705525415f,    0.23037781330885523f};
    const float FH[8] = {-0.23037781330885523f,   0.7148465705525415f,
                         -0.6308807679295904f,   -0.02798376941698385f,
                          0.18703481171888114f,   0.030841381835986965f,
                         -0.032883011666982945f, -0.010597401784997278f};

    const int tid = threadIdx.x;          // 0..255
    const int sy  = blockIdx.x;           // 0..31 stripe
    const int img = blockIdx.y;           // 0..95
    const int h0  = sy * TH;              // output row base
    const int r0  = 2 * h0;               // input row base

    const float* __restrict__ xin = x + (size_t)img * HH * WW;

    // ---- phase A: column pass, thread owns columns (2c, 2c+1), c = tid ----
    // One aligned u64 load per row IS the FFMA2 operand (adjacent pixels).
    {
        // dup coefficient pairs, hoisted into registers for the unrolled loop
        u64 CLd[8], CHd[8];
        #pragma unroll
        for (int t = 0; t < 8; t++) {
            CLd[t] = pk(FL[t], FL[t]);
            CHd[t] = pk(FH[t], FH[t]);
        }

        const int c = tid;
        u64 aLo[4], aHi[4];                // ring over j&3: (lo_c0,lo_c1),(hi_c0,hi_c1)
        #pragma unroll
        for (int k = 0; k < IN_R; k++) {
            int gr = (r0 + k) & (HH - 1);
            u64 v = *(const u64*)(xin + (size_t)gr * WW + 2 * c);
            #pragma unroll
            for (int j = 0; j < TH; j++) {
                const int t = k - 2 * j;
                if (t == 0) {
                    mul2(aLo[j & 3], CLd[0], v);
                    mul2(aHi[j & 3], CHd[0], v);
                } else if (t > 0 && t < 8) {
                    fma2(aLo[j & 3], CLd[t], v);
                    fma2(aHi[j & 3], CHd[t], v);
                }
                if (t == 7) {
                    *(u64*)&s_lo[j][2 * c] = aLo[j & 3];
                    *(u64*)&s_hi[j][2 * c] = aHi[j & 3];
                    if (c < 4) {                    // wrap halo cols 512..519
                        *(u64*)&s_lo[j][WW + 2 * c] = aLo[j & 3];
                        *(u64*)&s_hi[j][WW + 2 * c] = aHi[j & 3];
                    }
                }
            }
        }
    }
    __syncthreads();

    // ---- phase B: row pass from smem planes (scalar, proven) ----
    // item = (plane, j, wp): output cols 2wp, 2wp+1 of output row h0+j.
    float* __restrict__ outi = out + (size_t)img * 4 * OWW * OWW;
    const size_t SB = (size_t)OWW * OWW;

    #pragma unroll
    for (int it = 0; it < 8; it++) {
        int idx = tid + it * NT;             // 0..2047
        int wp  = idx & 127;                 // col-pair index
        int j   = (idx >> 7) & (TH - 1);     // 0..7
        int pl  = idx >> 10;                 // 0..1
        const float* __restrict__ A = pl ? &s_hi[j][0] : &s_lo[j][0];

        // window A[4wp .. 4wp+9]; 16B-stride contiguous -> conflict-free
        float4 q0 = *(const float4*)(A + 4 * wp);
        float4 q1 = *(const float4*)(A + 4 * wp + 4);
        float2 q2 = *(const float2*)(A + 4 * wp + 8);
        float v[10] = {q0.x, q0.y, q0.z, q0.w,
                       q1.x, q1.y, q1.z, q1.w,
                       q2.x, q2.y};

        float lo0 = 0.f, hi0 = 0.f, lo1 = 0.f, hi1 = 0.f;
        #pragma unroll
        for (int t = 0; t < 8; t++) {
            lo0 = fmaf(FL[t], v[t],     lo0);
            hi0 = fmaf(FH[t], v[t],     hi0);
            lo1 = fmaf(FL[t], v[t + 2], lo1);
            hi1 = fmaf(FH[t], v[t + 2], hi1);
        }

        int sbL = pl ? 1 : 0;    // row-lo result subband
        int sbH = pl ? 3 : 2;    // row-hi result subband
        size_t o = (size_t)(h0 + j) * OWW + 2 * wp;
        *(float2*)(outi + sbL * SB + o) = make_float2(lo0, lo1);
        *(float2*)(outi + sbH * SB + o) = make_float2(hi0, hi1);
    }
}

extern "C" void kernel_launch(void* const* d_in, const int* in_sizes, int n_in,
                              void* d_out, int out_size)
{
    const float* x = (const float*)d_in[0];   // (32,3,512,512) f32
    float* out = (float*)d_out;               // (32,12,256,256) f32

    dim3 grid(OWW / TH, 96);                  // (32 stripes, 96 images)
    dwt2d_db4_kernel<<<grid, NT>>>(x, out);
}